// round 10
// baseline (speedup 1.0000x reference)
#include <cuda_runtime.h>
#include <cuda_fp16.h>
#include <mma.h>
#include <cstdint>

using namespace nvcuda;

#define N_NODES_MAX 100000
#define NFEAT 128

// Scratch (allocation-free rule: __device__ globals, referenced only in kernels)
__device__ __half g_XFh[(size_t)N_NODES_MAX * NFEAT];   // XF in fp16
__device__ __half g_Fh[NFEAT * NFEAT];                  // filters in fp16
__device__ int    g_rowptr[N_NODES_MAX + 1];            // CSR row pointer

// ---------------------------------------------------------------------------
// Kernel A: rowptr from sorted edge_dst — 4 edges/thread, one int4 load.
// ---------------------------------------------------------------------------
__global__ void rowptr_kernel(const int* __restrict__ edst, int E, int N) {
    const int t  = blockIdx.x * blockDim.x + threadIdx.x;
    const int e0 = t * 4;
    if (e0 >= E) return;

    int d[4];
    int nvalid;
    if (e0 + 4 <= E) {
        const int4 d4 = __ldg((const int4*)(edst + e0));
        d[0] = d4.x; d[1] = d4.y; d[2] = d4.z; d[3] = d4.w;
        nvalid = 4;
    } else {
        nvalid = E - e0;
        for (int i = 0; i < nvalid; i++) d[i] = __ldg(edst + e0 + i);
    }

    int prev = (e0 == 0) ? -1 : __ldg(edst + e0 - 1);
#pragma unroll
    for (int i = 0; i < 4; i++) {
        if (i < nvalid) {
            for (int dd = prev + 1; dd <= d[i]; dd++) g_rowptr[dd] = e0 + i;
            prev = d[i];
        }
    }
    if (e0 + 4 >= E) {
        for (int dd = prev + 1; dd <= N; dd++) g_rowptr[dd] = E;
    }
}

// ---------------------------------------------------------------------------
// Kernel B0: filters fp32 -> fp16 (one-time tiny convert)
// ---------------------------------------------------------------------------
__global__ void fconv_kernel(const float* __restrict__ F) {
    int i = blockIdx.x * blockDim.x + threadIdx.x;
    if (i < NFEAT * NFEAT) g_Fh[i] = __float2half_rn(F[i]);
}

// ---------------------------------------------------------------------------
// Kernel B: tensor-core GEMM  XF[M,128] = x[M,128] @ filters[128,128]
// fp16 HMMA, fp32 accumulate, fp16 output. Filters staged in SMEM per block.
// ---------------------------------------------------------------------------
#define GB_BM 128
#define LDM 136   // 128 + 8 halves pad

__global__ __launch_bounds__(256)
void gemm_wmma_kernel(const float* __restrict__ A, int M) {
    __shared__ __half Bs[NFEAT][LDM];
    __shared__ __half As[GB_BM][LDM];
    __shared__ float  stage[8][16 * 16];

    const int tid  = threadIdx.x;
    const int warp = tid >> 5;
    const int lane = tid & 31;
    const int block_row = blockIdx.x * GB_BM;

#pragma unroll
    for (int i = 0; i < 8; i++) {
        const int g   = tid + i * 256;
        const int row = g >> 4;
        const int col = (g & 15) << 3;
        const uint4 v = *(const uint4*)(g_Fh + (size_t)row * NFEAT + col);
        *(uint4*)&Bs[row][col] = v;
    }

#pragma unroll
    for (int i = 0; i < 16; i++) {
        const int idx = tid + i * 256;
        const int row = idx >> 5;
        const int col = (idx & 31) << 2;
        const int gr  = block_row + row;
        float4 v;
        if (gr < M)
            v = *(const float4*)(A + (size_t)gr * NFEAT + col);
        else
            v = make_float4(0.f, 0.f, 0.f, 0.f);
        *(__half2*)&As[row][col + 0] = __floats2half2_rn(v.x, v.y);
        *(__half2*)&As[row][col + 2] = __floats2half2_rn(v.z, v.w);
    }
    __syncthreads();

    wmma::fragment<wmma::accumulator, 16, 16, 16, float> acc[8];
#pragma unroll
    for (int ct = 0; ct < 8; ct++) wmma::fill_fragment(acc[ct], 0.0f);

#pragma unroll
    for (int kt = 0; kt < 8; kt++) {
        wmma::fragment<wmma::matrix_a, 16, 16, 16, __half, wmma::row_major> a_frag;
        wmma::load_matrix_sync(a_frag, &As[warp * 16][kt * 16], LDM);
#pragma unroll
        for (int ct = 0; ct < 8; ct++) {
            wmma::fragment<wmma::matrix_b, 16, 16, 16, __half, wmma::row_major> b_frag;
            wmma::load_matrix_sync(b_frag, &Bs[kt * 16][ct * 16], LDM);
            wmma::mma_sync(acc[ct], a_frag, b_frag, acc[ct]);
        }
    }

    const int r  = lane >> 1;
    const int c0 = (lane & 1) * 8;
#pragma unroll
    for (int ct = 0; ct < 8; ct++) {
        wmma::store_matrix_sync(&stage[warp][0], acc[ct], 16, wmma::mem_row_major);
        __syncwarp();
        const float* sp = &stage[warp][r * 16 + c0];
        __half2 h[4];
#pragma unroll
        for (int j = 0; j < 4; j++)
            h[j] = __floats2half2_rn(sp[2 * j], sp[2 * j + 1]);
        const int gr = block_row + warp * 16 + r;
        if (gr < M)
            *(uint4*)(g_XFh + (size_t)gr * NFEAT + ct * 16 + c0) = *(const uint4*)h;
        __syncwarp();
    }
}

// ---------------------------------------------------------------------------
// Kernel C: SpMM — warp per dst node. fp16 HFMA2 accumulation, fp32 flush
// every 4 edges (kills the 4 F2F + 4 FFMA per edge of the fp32 path).
// ---------------------------------------------------------------------------
__device__ __forceinline__ void edge_h(__half2& a0, __half2& a1,
                                       int s, float w, int lane) {
    const uint2 hv = *(const uint2*)(g_XFh + (size_t)s * NFEAT + lane * 4);
    const __half2 wh = __float2half2_rn(w);           // 1 cvt (dup)
    a0 = __hfma2(wh, *reinterpret_cast<const __half2*>(&hv.x), a0);
    a1 = __hfma2(wh, *reinterpret_cast<const __half2*>(&hv.y), a1);
}

__device__ __forceinline__ void flush_h(float4& f, __half2& a0, __half2& a1) {
    const float2 p = __half22float2(a0);
    const float2 q = __half22float2(a1);
    f.x += p.x; f.y += p.y; f.z += q.x; f.w += q.y;
    const __half2 z = __float2half2_rn(0.f);
    a0 = z; a1 = z;
}

__global__ __launch_bounds__(256)
void spmm_kernel(const int* __restrict__ esrc,
                 const float* __restrict__ ew,
                 float* __restrict__ out,
                 int N) {
    const int warp = (blockIdx.x * blockDim.x + threadIdx.x) >> 5;
    const int lane = threadIdx.x & 31;
    if (warp >= N) return;

    const int start = g_rowptr[warp];
    const int end   = g_rowptr[warp + 1];

    float4  acc = make_float4(0.f, 0.f, 0.f, 0.f);
    __half2 a0  = __float2half2_rn(0.f);
    __half2 a1  = a0;

    int e = start;
    // Head: reach 16B alignment (immediate flush keeps fp16 chains short)
    while (e < end && (e & 3)) {
        edge_h(a0, a1, __ldg(esrc + e), __ldg(ew + e), lane);
        e++;
    }
    if (e > start) flush_h(acc, a0, a1);

    // Main: 8 edges per iteration = two 4-edge fp16 groups, flush after each
    for (; e + 8 <= end; e += 8) {
        const int4   sa = __ldg((const int4*)(esrc + e));
        const int4   sb = __ldg((const int4*)(esrc + e + 4));
        const float4 wa = __ldg((const float4*)(ew + e));
        const float4 wb = __ldg((const float4*)(ew + e + 4));
        edge_h(a0, a1, sa.x, wa.x, lane);
        edge_h(a0, a1, sa.y, wa.y, lane);
        edge_h(a0, a1, sa.z, wa.z, lane);
        edge_h(a0, a1, sa.w, wa.w, lane);
        flush_h(acc, a0, a1);
        edge_h(a0, a1, sb.x, wb.x, lane);
        edge_h(a0, a1, sb.y, wb.y, lane);
        edge_h(a0, a1, sb.z, wb.z, lane);
        edge_h(a0, a1, sb.w, wb.w, lane);
        flush_h(acc, a0, a1);
    }
    // Mid: one 4-edge block
    for (; e + 4 <= end; e += 4) {
        const int4   sa = __ldg((const int4*)(esrc + e));
        const float4 wa = __ldg((const float4*)(ew + e));
        edge_h(a0, a1, sa.x, wa.x, lane);
        edge_h(a0, a1, sa.y, wa.y, lane);
        edge_h(a0, a1, sa.z, wa.z, lane);
        edge_h(a0, a1, sa.w, wa.w, lane);
        flush_h(acc, a0, a1);
    }
    // Tail
    for (; e < end; e++)
        edge_h(a0, a1, __ldg(esrc + e), __ldg(ew + e), lane);
    if (end > start) flush_h(acc, a0, a1);

    *(float4*)(out + (size_t)warp * NFEAT + (size_t)lane * 4) = acc;
}

// ---------------------------------------------------------------------------
// Launch: rowptr -> fconv -> gemm -> spmm (graph-capturable)
// ---------------------------------------------------------------------------
extern "C" void kernel_launch(void* const* d_in, const int* in_sizes, int n_in,
                              void* d_out, int out_size) {
    const float* x       = (const float*)d_in[0];
    const float* filters = (const float*)d_in[1];
    const int*   esrc    = (const int*)d_in[2];
    const int*   edst    = (const int*)d_in[3];
    const float* ew      = (const float*)d_in[4];
    float*       out     = (float*)d_out;

    const int M = in_sizes[0] / NFEAT;   // 100000 nodes
    const int E = in_sizes[4];           // 3200000 edges

    const int rthreads = (E + 3) / 4;
    rowptr_kernel<<<(rthreads + 255) / 256, 256>>>(edst, E, M);
    fconv_kernel<<<(NFEAT * NFEAT + 255) / 256, 256>>>(filters);
    gemm_wmma_kernel<<<(M + GB_BM - 1) / GB_BM, 256>>>(x, M);

    const long long nthreads = (long long)M * 32;
    spmm_kernel<<<(int)((nthreads + 255) / 256), 256>>>(esrc, ew, out, M);
}

// round 12
// speedup vs baseline: 1.1272x; 1.1272x over previous
#include <cuda_runtime.h>
#include <cuda_fp16.h>
#include <mma.h>
#include <cstdint>

using namespace nvcuda;

#define N_NODES_MAX 100000
#define NFEAT 128

// Scratch (allocation-free rule: __device__ globals, referenced only in kernels)
__device__ __half g_XFh[(size_t)N_NODES_MAX * NFEAT];   // XF in fp16
__device__ __half g_Fh[NFEAT * NFEAT];                  // filters in fp16
__device__ int    g_rowptr[N_NODES_MAX + 1];            // CSR row pointer

// ---------------------------------------------------------------------------
// Kernel A: rowptr from sorted edge_dst — 4 edges/thread, one int4 load.
// ---------------------------------------------------------------------------
__global__ void rowptr_kernel(const int* __restrict__ edst, int E, int N) {
    const int t  = blockIdx.x * blockDim.x + threadIdx.x;
    const int e0 = t * 4;
    if (e0 >= E) return;

    int d[4];
    int nvalid;
    if (e0 + 4 <= E) {
        const int4 d4 = __ldg((const int4*)(edst + e0));
        d[0] = d4.x; d[1] = d4.y; d[2] = d4.z; d[3] = d4.w;
        nvalid = 4;
    } else {
        nvalid = E - e0;
        for (int i = 0; i < nvalid; i++) d[i] = __ldg(edst + e0 + i);
    }

    int prev = (e0 == 0) ? -1 : __ldg(edst + e0 - 1);
#pragma unroll
    for (int i = 0; i < 4; i++) {
        if (i < nvalid) {
            for (int dd = prev + 1; dd <= d[i]; dd++) g_rowptr[dd] = e0 + i;
            prev = d[i];
        }
    }
    if (e0 + 4 >= E) {
        for (int dd = prev + 1; dd <= N; dd++) g_rowptr[dd] = E;
    }
}

// ---------------------------------------------------------------------------
// Kernel B0: filters fp32 -> fp16 (one-time tiny convert)
// ---------------------------------------------------------------------------
__global__ void fconv_kernel(const float* __restrict__ F) {
    int i = blockIdx.x * blockDim.x + threadIdx.x;
    if (i < NFEAT * NFEAT) g_Fh[i] = __float2half_rn(F[i]);
}

// ---------------------------------------------------------------------------
// Kernel B: tensor-core GEMM  XF[M,128] = x[M,128] @ filters[128,128]
// fp16 HMMA, fp32 accumulate, fp16 output.
// BM=64, 256 threads / 8 warps: warp w -> rows [(w>>1)*16, +16),
// cols [(w&1)*64, +64) (4 col tiles). ~60KB SMEM -> 3 blocks/SM.
// ---------------------------------------------------------------------------
#define GB_BM 64
#define LDM 136   // 128 + 8 halves pad

__global__ __launch_bounds__(256)
void gemm_wmma_kernel(const float* __restrict__ A, int M) {
    __shared__ __half Bs[NFEAT][LDM];          // filters, 34.8KB
    __shared__ __half As[GB_BM][LDM];          // x tile fp16, 17.4KB
    __shared__ float  stage[8][16 * 16];       // per-warp staging, 8KB

    const int tid  = threadIdx.x;
    const int warp = tid >> 5;
    const int lane = tid & 31;
    const int block_row = blockIdx.x * GB_BM;

    // Stage filters: 2048 uint4 groups; 8 per thread (coalesced)
#pragma unroll
    for (int i = 0; i < 8; i++) {
        const int g   = tid + i * 256;
        const int row = g >> 4;
        const int col = (g & 15) << 3;
        const uint4 v = *(const uint4*)(g_Fh + (size_t)row * NFEAT + col);
        *(uint4*)&Bs[row][col] = v;
    }

    // Load + convert x tile: 64x128 fp32 -> fp16 SMEM (8 float4 per thread)
#pragma unroll
    for (int i = 0; i < 8; i++) {
        const int idx = tid + i * 256;          // 0..2047
        const int row = idx >> 5;
        const int col = (idx & 31) << 2;
        const int gr  = block_row + row;
        float4 v;
        if (gr < M)
            v = *(const float4*)(A + (size_t)gr * NFEAT + col);
        else
            v = make_float4(0.f, 0.f, 0.f, 0.f);
        *(__half2*)&As[row][col + 0] = __floats2half2_rn(v.x, v.y);
        *(__half2*)&As[row][col + 2] = __floats2half2_rn(v.z, v.w);
    }
    __syncthreads();

    // MMA: warp owns 16 rows x 64 cols
    const int srow = (warp >> 1) * 16;
    const int scol = (warp & 1) * 64;

    wmma::fragment<wmma::accumulator, 16, 16, 16, float> acc[4];
#pragma unroll
    for (int ct = 0; ct < 4; ct++) wmma::fill_fragment(acc[ct], 0.0f);

#pragma unroll
    for (int kt = 0; kt < 8; kt++) {
        wmma::fragment<wmma::matrix_a, 16, 16, 16, __half, wmma::row_major> a_frag;
        wmma::load_matrix_sync(a_frag, &As[srow][kt * 16], LDM);
#pragma unroll
        for (int ct = 0; ct < 4; ct++) {
            wmma::fragment<wmma::matrix_b, 16, 16, 16, __half, wmma::row_major> b_frag;
            wmma::load_matrix_sync(b_frag, &Bs[kt * 16][scol + ct * 16], LDM);
            wmma::mma_sync(acc[ct], a_frag, b_frag, acc[ct]);
        }
    }

    // Store: stage f32 per col-tile, convert to fp16, 16B/thread writes
    const int r  = lane >> 1;
    const int c0 = (lane & 1) * 8;
#pragma unroll
    for (int ct = 0; ct < 4; ct++) {
        wmma::store_matrix_sync(&stage[warp][0], acc[ct], 16, wmma::mem_row_major);
        __syncwarp();
        const float* sp = &stage[warp][r * 16 + c0];
        __half2 h[4];
#pragma unroll
        for (int j = 0; j < 4; j++)
            h[j] = __floats2half2_rn(sp[2 * j], sp[2 * j + 1]);
        const int gr = block_row + srow + r;
        if (gr < M)
            *(uint4*)(g_XFh + (size_t)gr * NFEAT + scol + ct * 16 + c0) = *(const uint4*)h;
        __syncwarp();
    }
}

// ---------------------------------------------------------------------------
// Kernel C: SpMM — warp per dst node, fp32 accumulation (round-7 numerics).
// 8-edge body with ALL gathers issued before converts/FMAs (explicit MLP=8),
// two accumulator chains to shorten FFMA dependency chains.
// ---------------------------------------------------------------------------
__device__ __forceinline__ void cvt_fma(float4& acc, uint2 hv, float w) {
    const float2 f0 = __half22float2(*reinterpret_cast<const __half2*>(&hv.x));
    const float2 f1 = __half22float2(*reinterpret_cast<const __half2*>(&hv.y));
    acc.x += w * f0.x;
    acc.y += w * f0.y;
    acc.z += w * f1.x;
    acc.w += w * f1.y;
}

__global__ __launch_bounds__(256)
void spmm_kernel(const int* __restrict__ esrc,
                 const float* __restrict__ ew,
                 float* __restrict__ out,
                 int N) {
    const int warp = (blockIdx.x * blockDim.x + threadIdx.x) >> 5;
    const int lane = threadIdx.x & 31;
    if (warp >= N) return;

    const int start = g_rowptr[warp];
    const int end   = g_rowptr[warp + 1];

    const __half* __restrict__ base = g_XFh + lane * 4;   // lane offset folded

    float4 acc0 = make_float4(0.f, 0.f, 0.f, 0.f);
    float4 acc1 = make_float4(0.f, 0.f, 0.f, 0.f);

    int e = start;
    // Head: reach 16B alignment for vector index loads
    while (e < end && (e & 3)) {
        const uint2 hv = *(const uint2*)(base + (size_t)__ldg(esrc + e) * NFEAT);
        cvt_fma(acc0, hv, __ldg(ew + e));
        e++;
    }
    // Main: 8 edges — batch all 8 gathers first, then math
    for (; e + 8 <= end; e += 8) {
        const int4   sa = __ldg((const int4*)(esrc + e));
        const int4   sb = __ldg((const int4*)(esrc + e + 4));
        const float4 wa = __ldg((const float4*)(ew + e));
        const float4 wb = __ldg((const float4*)(ew + e + 4));
        uint2 hv[8];
        hv[0] = *(const uint2*)(base + (size_t)sa.x * NFEAT);
        hv[1] = *(const uint2*)(base + (size_t)sa.y * NFEAT);
        hv[2] = *(const uint2*)(base + (size_t)sa.z * NFEAT);
        hv[3] = *(const uint2*)(base + (size_t)sa.w * NFEAT);
        hv[4] = *(const uint2*)(base + (size_t)sb.x * NFEAT);
        hv[5] = *(const uint2*)(base + (size_t)sb.y * NFEAT);
        hv[6] = *(const uint2*)(base + (size_t)sb.z * NFEAT);
        hv[7] = *(const uint2*)(base + (size_t)sb.w * NFEAT);
        cvt_fma(acc0, hv[0], wa.x);
        cvt_fma(acc1, hv[1], wa.y);
        cvt_fma(acc0, hv[2], wa.z);
        cvt_fma(acc1, hv[3], wa.w);
        cvt_fma(acc0, hv[4], wb.x);
        cvt_fma(acc1, hv[5], wb.y);
        cvt_fma(acc0, hv[6], wb.z);
        cvt_fma(acc1, hv[7], wb.w);
    }
    // Mid: one 4-edge block
    for (; e + 4 <= end; e += 4) {
        const int4   sa = __ldg((const int4*)(esrc + e));
        const float4 wa = __ldg((const float4*)(ew + e));
        uint2 hv[4];
        hv[0] = *(const uint2*)(base + (size_t)sa.x * NFEAT);
        hv[1] = *(const uint2*)(base + (size_t)sa.y * NFEAT);
        hv[2] = *(const uint2*)(base + (size_t)sa.z * NFEAT);
        hv[3] = *(const uint2*)(base + (size_t)sa.w * NFEAT);
        cvt_fma(acc0, hv[0], wa.x);
        cvt_fma(acc1, hv[1], wa.y);
        cvt_fma(acc0, hv[2], wa.z);
        cvt_fma(acc1, hv[3], wa.w);
    }
    // Tail
    for (; e < end; e++) {
        const uint2 hv = *(const uint2*)(base + (size_t)__ldg(esrc + e) * NFEAT);
        cvt_fma(acc0, hv, __ldg(ew + e));
    }

    const float4 r = make_float4(acc0.x + acc1.x, acc0.y + acc1.y,
                                 acc0.z + acc1.z, acc0.w + acc1.w);
    *(float4*)(out + (size_t)warp * NFEAT + (size_t)lane * 4) = r;
}

// ---------------------------------------------------------------------------
// Launch: rowptr -> fconv -> gemm -> spmm (graph-capturable)
// ---------------------------------------------------------------------------
extern "C" void kernel_launch(void* const* d_in, const int* in_sizes, int n_in,
                              void* d_out, int out_size) {
    const float* x       = (const float*)d_in[0];
    const float* filters = (const float*)d_in[1];
    const int*   esrc    = (const int*)d_in[2];
    const int*   edst    = (const int*)d_in[3];
    const float* ew      = (const float*)d_in[4];
    float*       out     = (float*)d_out;

    const int M = in_sizes[0] / NFEAT;   // 100000 nodes
    const int E = in_sizes[4];           // 3200000 edges

    const int rthreads = (E + 3) / 4;
    rowptr_kernel<<<(rthreads + 255) / 256, 256>>>(edst, E, M);
    fconv_kernel<<<(NFEAT * NFEAT + 255) / 256, 256>>>(filters);
    gemm_wmma_kernel<<<(M + GB_BM - 1) / GB_BM, 256>>>(x, M);

    const long long nthreads = (long long)M * 32;
    spmm_kernel<<<(int)((nthreads + 255) / 256), 256>>>(esrc, ew, out, M);
}